// round 6
// baseline (speedup 1.0000x reference)
#include <cuda_runtime.h>
#include <cuda_bf16.h>

// ---------------------------------------------------------------------------
// FocalLoss + ArcFace, B x C (4096 x 32768 f32), targets int32, scalar f32 out.
//
// One CTA per row; row streamed from HBM exactly once (LDG.128) with fp32
// sum-of-squares via packed fma.rn.f32x2, staged bf16 in SMEM (64KB -> 3
// CTAs/SM). Pass 2: bf16x2 mul + ex2.approx.ftz.bf16x2 (2 exps per MUFU op),
// HADD2 tree per uint4, f32 accumulation. |logit| <= 30 so no max-subtract.
// Target column fixed up in exact fp32 (bf16 pipeline replicated for the
// subtraction term). Last-arriving CTA (ticket) reduces per-row losses and
// writes the mean -> single kernel launch.
// ---------------------------------------------------------------------------

#define ROW_THREADS 512
#define MAX_B 16384
#define LOG2E 1.4426950408889634f

__device__ float g_rowloss[MAX_B];
__device__ unsigned int g_ticket = 0;

__device__ __forceinline__ unsigned bmul2(unsigned a, unsigned b) {
    unsigned d; asm("mul.rn.bf16x2 %0, %1, %2;" : "=r"(d) : "r"(a), "r"(b)); return d;
}
__device__ __forceinline__ unsigned badd2(unsigned a, unsigned b) {
    unsigned d; asm("add.rn.bf16x2 %0, %1, %2;" : "=r"(d) : "r"(a), "r"(b)); return d;
}
__device__ __forceinline__ unsigned bex2(unsigned a) {
    unsigned d; asm("ex2.approx.ftz.bf16x2 %0, %1;" : "=r"(d) : "r"(a)); return d;
}
// packed acc += v*v (two fp32 lanes)
__device__ __forceinline__ void ffma2_sq(unsigned long long& acc, unsigned long long v) {
    asm("fma.rn.f32x2 %0, %1, %1, %0;" : "+l"(acc) : "l"(v));
}
__device__ __forceinline__ unsigned long long pack2(float lo, float hi) {
    unsigned long long d;
    asm("mov.b64 %0, {%1, %2};" : "=l"(d) : "f"(lo), "f"(hi));
    return d;
}

// Block-wide sum; internal syncs also publish prior SMEM writes, trailing
// sync allows `red` reuse across calls.
__device__ __forceinline__ float block_reduce_sum(float v, float* red, int tid) {
    #pragma unroll
    for (int o = 16; o > 0; o >>= 1) v += __shfl_xor_sync(0xffffffffu, v, o);
    const int warp = tid >> 5, lane = tid & 31;
    if (lane == 0) red[warp] = v;
    __syncthreads();
    if (warp == 0) {
        v = (lane < (ROW_THREADS / 32)) ? red[lane] : 0.0f;
        #pragma unroll
        for (int o = 16; o > 0; o >>= 1) v += __shfl_xor_sync(0xffffffffu, v, o);
        if (lane == 0) red[0] = v;
    }
    __syncthreads();
    float r = red[0];
    __syncthreads();
    return r;
}

__global__ __launch_bounds__(ROW_THREADS, 3)
void focal_arcface_row_kernel(const float* __restrict__ x,
                              const int* __restrict__ tgt,
                              int C, float* __restrict__ out) {
    extern __shared__ __nv_bfloat16 buf[];   // C bf16 (64KB for C=32768)
    __shared__ float red[ROW_THREADS / 32];
    __shared__ unsigned is_last;

    const int row = blockIdx.x;
    const int tid = threadIdx.x;
    const float4* __restrict__ xr =
        reinterpret_cast<const float4*>(x + (size_t)row * (size_t)C);
    uint2* __restrict__ buf2 = reinterpret_cast<uint2*>(buf);
    const int n4 = C >> 2;

    // ---- Pass 1: stream row once, packed fp32 sumsq, stage bf16 ----
    unsigned long long a0 = 0ull, a1 = 0ull;
    #pragma unroll 4
    for (int j = tid; j < n4; j += ROW_THREADS) {
        float4 v = xr[j];
        ffma2_sq(a0, pack2(v.x, v.y));
        ffma2_sq(a1, pack2(v.z, v.w));
        __nv_bfloat162 lo = __floats2bfloat162_rn(v.x, v.y);
        __nv_bfloat162 hi = __floats2bfloat162_rn(v.z, v.w);
        uint2 p;
        p.x = *reinterpret_cast<unsigned*>(&lo);
        p.y = *reinterpret_cast<unsigned*>(&hi);
        buf2[j] = p;
    }
    float s0, s1, s2, s3;
    asm("mov.b64 {%0, %1}, %2;" : "=f"(s0), "=f"(s1) : "l"(a0));
    asm("mov.b64 {%0, %1}, %2;" : "=f"(s2), "=f"(s3) : "l"(a1));
    float ss = (s0 + s1) + (s2 + s3);

    float sumsq = block_reduce_sum(ss, red, tid);   // also publishes buf[]
    float norm  = fmaxf(sqrtf(sumsq), 1e-12f);
    float k     = (30.0f / norm) * LOG2E;           // exp(s*x) == exp2(k*x)

    unsigned k2;
    {
        __nv_bfloat162 kk = __floats2bfloat162_rn(k, k);
        k2 = *reinterpret_cast<unsigned*>(&kk);
    }

    // ---- Pass 2: sum exp2(k*x) over all columns, bf16x2 pipeline ----
    const uint4* __restrict__ buf4 = reinterpret_cast<const uint4*>(buf);
    const int n8 = C >> 3;
    float se = 0.0f;
    #pragma unroll 4
    for (int j = tid; j < n8; j += ROW_THREADS) {
        uint4 p = buf4[j];
        unsigned e0 = bex2(bmul2(p.x, k2));
        unsigned e1 = bex2(bmul2(p.y, k2));
        unsigned e2 = bex2(bmul2(p.z, k2));
        unsigned e3 = bex2(bmul2(p.w, k2));
        unsigned h  = badd2(badd2(e0, e1), badd2(e2, e3));
        se += __uint_as_float(h << 16) + __uint_as_float(h & 0xffff0000u);
    }
    float sum_all = block_reduce_sum(se, red, tid);

    // ---- Per-row scalar epilogue + ticketed final reduce ----
    if (tid == 0) {
        int t = tgt[row];
        t = (t < 0) ? 0 : (t >= C ? C - 1 : t);               // defensive clamp
        float xt = x[(size_t)row * (size_t)C + (size_t)t];    // exact fp32

        // cos(theta), clipped like the reference; exact angle-addition identity
        float c = xt / norm;
        c = fminf(fmaxf(c, -1.0f + 1e-7f), 1.0f - 1e-7f);
        const float cosM = 0.95533648912560601964f;   // cos(0.3)
        const float sinM = 0.29552020666133957511f;   // sin(0.3)
        float cosm = c * cosM - sqrtf(fmaxf(1.0f - c * c, 0.0f)) * sinM;
        float lt = 30.0f * cosm;                      // target logit

        // Remove the target's pass-2 term via the IDENTICAL bf16 lane pipeline
        unsigned short raw = *reinterpret_cast<unsigned short*>(&buf[t]);
        unsigned tb = (unsigned)raw | ((unsigned)raw << 16);
        unsigned te = bex2(bmul2(tb, k2));
        float term = __uint_as_float(te << 16);       // lane0

        float sum = sum_all - term + expf(lt);
        float lse = logf(sum);                        // |logit|<=30: no max needed
        float ce  = lse - lt;
        float pt  = expf(-ce);
        float om  = 1.0f - pt;
        g_rowloss[row] = om * om * ce;                // gamma = 2

        __threadfence();                              // release rowloss write
        unsigned done = atomicAdd(&g_ticket, 1u);
        is_last = (done == gridDim.x - 1) ? 1u : 0u;
        if (is_last) __threadfence();                 // acquire others' writes
    }
    __syncthreads();

    if (is_last) {
        const int B = gridDim.x;
        float v = 0.0f;
        for (int i = tid; i < B; i += ROW_THREADS) v += __ldcg(&g_rowloss[i]);
        v = block_reduce_sum(v, red, tid);
        if (tid == 0) {
            out[0] = v / (float)B;
            g_ticket = 0;                             // reset for next replay
        }
    }
}

extern "C" void kernel_launch(void* const* d_in, const int* in_sizes, int n_in,
                              void* d_out, int out_size) {
    // Identify slots by size: big buffer = inputs, small = targets.
    int xi = 0, ti = 1;
    if (n_in >= 2 && in_sizes[1] > in_sizes[0]) { xi = 1; ti = 0; }

    const float* x   = (const float*)d_in[xi];
    const int*   tgt = (const int*)d_in[ti];     // int64 lowered to i32 by harness

    const int B = in_sizes[ti];
    const int C = in_sizes[xi] / B;

    const size_t smem = (size_t)C * sizeof(__nv_bfloat16);  // 64KB for C=32768
    cudaFuncSetAttribute(focal_arcface_row_kernel,
                         cudaFuncAttributeMaxDynamicSharedMemorySize,
                         (int)smem);

    focal_arcface_row_kernel<<<B, ROW_THREADS, smem>>>(x, tgt, C, (float*)d_out);
}